// round 14
// baseline (speedup 1.0000x reference)
#include <cuda_runtime.h>
#include <cuda_fp16.h>
#include <cstdint>
#include <cstddef>

#define H    1024
#define FF   2048
#define G3   3072
#define SEQ  64
#define T    30
#define NSEG 8
#define SUB  4
#define R    240
#define RP   256
#define DT   (1.0f/32.0f)
#define NB   128
#define NWARP (NB*8)
#define SNB  288
#define KS   2
#define KC   512
#define BM   128
#define BN   128
#define MX   (T*SEQ)

#define TB   10240
#define SETB (2*TB)
#define DSM  (2*SETB)   // 40960

typedef unsigned long long ull;

// ---------------- scratch ----------------------------------------------------
__device__ float g_h[H], g_heff[H], g_t1[FF], g_t2[FF];
__device__ float g_traj[NSEG][H];
__device__ __align__(16) float g_gi0[(size_t)MX * G3];
__device__ __align__(16) float g_h1[2][RP * H];
__device__ __align__(16) float g_h2[2][RP * H];
__device__ __align__(16) float g_P0[(size_t)KS * RP * G3];
__device__ __align__(16) float g_PI[(size_t)KS * RP * G3];
__device__ __align__(16) float g_PH[(size_t)KS * RP * G3];
__device__ __align__(16) __half g_W16[4ull * G3 * H];   // wh0, wi1, wh1, wi0
__device__ __align__(16) __half g_A16[4ull * RP * H];   // h1[0],h1[1],h2[0],h2[1]
__device__ __align__(16) __half g_X16[(size_t)MX * H];

// tree barriers: leaf counters in separate 128B lines
__device__ unsigned g_leafA[8 * 32],  g_rootA, g_gen;    // ODE (128 CTAs, 8x16)
__device__ unsigned g_leafB[16 * 32], g_rootB, g_gen2;   // steps (288 CTAs, 16x18)

__device__ __forceinline__ float sigf(float v) { return 1.f / (1.f + expf(-v)); }

// ---- mma / async helpers ----------------------------------------------------
__device__ __forceinline__ uint32_t smem_u32(const void* p) {
    uint32_t a;
    asm("{ .reg .u64 t; cvta.to.shared.u64 t, %1; cvt.u32.u64 %0, t; }"
        : "=r"(a) : "l"(p));
    return a;
}
__device__ __forceinline__ void ldsm4(unsigned* r, uint32_t addr) {
    asm volatile("ldmatrix.sync.aligned.m8n8.x4.shared.b16 {%0,%1,%2,%3},[%4];"
                 : "=r"(r[0]), "=r"(r[1]), "=r"(r[2]), "=r"(r[3]) : "r"(addr));
}
__device__ __forceinline__ void mma16816(float* c, const unsigned* a,
                                         const unsigned* b) {
    asm volatile(
        "mma.sync.aligned.m16n8k16.row.col.f32.f16.f16.f32 "
        "{%0,%1,%2,%3},{%4,%5,%6,%7},{%8,%9},{%0,%1,%2,%3};"
        : "+f"(c[0]), "+f"(c[1]), "+f"(c[2]), "+f"(c[3])
        : "r"(a[0]), "r"(a[1]), "r"(a[2]), "r"(a[3]), "r"(b[0]), "r"(b[1]));
}
__device__ __forceinline__ void cp16ca(uint32_t dst, const void* src) {
    asm volatile("cp.async.ca.shared.global.L2::128B [%0],[%1],16;"
                 :: "r"(dst), "l"(src));
}
__device__ __forceinline__ void cp16cg(uint32_t dst, const void* src) {
    asm volatile("cp.async.cg.shared.global.L2::128B [%0],[%1],16;"
                 :: "r"(dst), "l"(src));
}
#define CPCOMMIT() asm volatile("cp.async.commit_group;" ::: "memory")
#define CPWAIT1()  asm volatile("cp.async.wait_group 1;" ::: "memory")
#define CPWAIT0()  asm volatile("cp.async.wait_group 0;" ::: "memory")

// ---- two-level tree barrier --------------------------------------------------
__device__ __forceinline__ void tbar(unsigned* leaf, unsigned* root,
                                     unsigned* gen, int grp, unsigned ng,
                                     unsigned G, unsigned base, unsigned idx) {
    __syncthreads();
    if (threadIdx.x == 0) {
        bool done = false;
        unsigned old;
        asm volatile("atom.acq_rel.gpu.global.add.u32 %0, [%1], 1;"
                     : "=r"(old) : "l"(leaf + grp * 32) : "memory");
        if (old == ng - 1) {
            asm volatile("st.relaxed.gpu.global.u32 [%0], 0;"
                         :: "l"(leaf + grp * 32) : "memory");
            unsigned o2;
            asm volatile("atom.acq_rel.gpu.global.add.u32 %0, [%1], 1;"
                         : "=r"(o2) : "l"(root) : "memory");
            if (o2 == G - 1) {
                asm volatile("st.relaxed.gpu.global.u32 [%0], 0;"
                             :: "l"(root) : "memory");
                unsigned d;
                asm volatile("atom.release.gpu.global.add.u32 %0, [%1], 1;"
                             : "=r"(d) : "l"(gen) : "memory");
                done = true;
            }
        }
        if (!done) {
            unsigned g;
            do {
                asm volatile("ld.acquire.gpu.global.u32 %0, [%1];"
                             : "=r"(g) : "l"(gen) : "memory");
            } while ((g - base) < idx);
        }
    }
    __syncthreads();
}

// =================== persistent ODE kernel (fp32 weights, as R12) ===========
__device__ __forceinline__ float2 rowdot2(const float* __restrict__ w0,
                                          const float* __restrict__ w1,
                                          const float* __restrict__ sv,
                                          int K, int lane) {
    float s0 = 0.f, s1 = 0.f;
#pragma unroll 4
    for (int k = lane * 4; k < K; k += 128) {
        float4 a = *(const float4*)(w0 + k);
        float4 b = *(const float4*)(w1 + k);
        float4 v = *(const float4*)(sv + k);
        s0 += a.x * v.x + a.y * v.y + a.z * v.z + a.w * v.w;
        s1 += b.x * v.x + b.y * v.y + b.z * v.z + b.w * v.w;
    }
#pragma unroll
    for (int o = 16; o; o >>= 1) {
        s0 += __shfl_xor_sync(0xffffffffu, s0, o);
        s1 += __shfl_xor_sync(0xffffffffu, s1, o);
    }
    return make_float2(s0, s1);
}

__device__ __forceinline__ float rowdot(const float* __restrict__ wr,
                                        const float* __restrict__ sv,
                                        int K, int lane) {
    float s = 0.f;
#pragma unroll 8
    for (int k = lane * 4; k < K; k += 128) {
        float4 w = *(const float4*)(wr + k);
        float4 v = *(const float4*)(sv + k);
        s += w.x * v.x + w.y * v.y + w.z * v.z + w.w * v.w;
    }
#pragma unroll
    for (int o = 16; o; o >>= 1) s += __shfl_xor_sync(0xffffffffu, s, o);
    return s;
}

__global__ void __launch_bounds__(256, 1) ode_all(
    const float* __restrict__ w1, const float* __restrict__ b1,
    const float* __restrict__ w2, const float* __restrict__ b2,
    const float* __restrict__ w3, const float* __restrict__ b3) {
    __shared__ __align__(16) float sv[FF];
    __shared__ unsigned sbase;
    int tid = threadIdx.x, lane = tid & 31, warp = tid >> 5;
    int wg = blockIdx.x * 8 + warp;
    int grp = blockIdx.x >> 4;          // 8 groups of 16

    if (tid == 0) sbase = *(volatile unsigned*)&g_gen;
    if (blockIdx.x == 0)
        for (int i = tid; i < H; i += 256) __stcg(&g_h[i], 0.f);
    __syncthreads();
    unsigned base = sbase, bi = 0;
    tbar(g_leafA, &g_rootA, &g_gen, grp, 16, 8, base, ++bi);

    float hreg = 0.f, ks = 0.f;

    for (int iv = 0; iv < NSEG; iv++)
    for (int sb = 0; sb < SUB; sb++)
    for (int m = 0; m < 4; m++) {
        const float* vsrc = (m == 0) ? g_h : g_heff;
        for (int i = tid; i < H; i += 256) sv[i] = __ldcg(vsrc + i);
        __syncthreads();
        {   // stage 1 (2048 rows / 1024 warps)
            float2 s = rowdot2(w1 + (size_t)wg * H,
                               w1 + (size_t)(wg + NWARP) * H, sv, H, lane);
            if (lane == 0) {
                __stcg(&g_t1[wg],         tanhf(s.x + b1[wg]));
                __stcg(&g_t1[wg + NWARP], tanhf(s.y + b1[wg + NWARP]));
            }
        }
        tbar(g_leafA, &g_rootA, &g_gen, grp, 16, 8, base, ++bi);

        for (int i = tid; i < FF; i += 256) sv[i] = __ldcg(&g_t1[i]);
        __syncthreads();
        {   // stage 2
            float2 s = rowdot2(w2 + (size_t)wg * FF,
                               w2 + (size_t)(wg + NWARP) * FF, sv, FF, lane);
            if (lane == 0) {
                __stcg(&g_t2[wg],         tanhf(s.x + b2[wg]));
                __stcg(&g_t2[wg + NWARP], tanhf(s.y + b2[wg + NWARP]));
            }
        }
        tbar(g_leafA, &g_rootA, &g_gen, grp, 16, 8, base, ++bi);

        for (int i = tid; i < FF; i += 256) sv[i] = __ldcg(&g_t2[i]);
        __syncthreads();
        if (wg < H) {   // stage 3 + RK4 combine
            float s = rowdot(w3 + (size_t)wg * FF, sv, FF, lane);
            if (lane == 0) {
                float kv = s + b3[wg];
                if (m == 0)      { ks = kv;          __stcg(&g_heff[wg], hreg + 0.5f * DT * kv); }
                else if (m == 1) { ks += 2.f * kv;   __stcg(&g_heff[wg], hreg + 0.5f * DT * kv); }
                else if (m == 2) { ks += 2.f * kv;   __stcg(&g_heff[wg], hreg + DT * kv); }
                else {
                    hreg += (DT / 6.f) * (ks + kv);
                    __stcg(&g_h[wg], hreg);
                    if (sb == SUB - 1) g_traj[iv][wg] = hreg;
                }
            }
        }
        tbar(g_leafA, &g_rootA, &g_gen, grp, 16, 8, base, ++bi);
    }
}

// ---------------- fp16 conversions -------------------------------------------
__global__ void wcvt4(const float* __restrict__ w0, const float* __restrict__ w1,
                      const float* __restrict__ w2, const float* __restrict__ w3) {
    int m = blockIdx.y;
    const float* src = (m == 0) ? w0 : (m == 1) ? w1 : (m == 2) ? w2 : w3;
    size_t i = (size_t)blockIdx.x * 256 + threadIdx.x;
    g_W16[(size_t)m * G3 * H + i] = __float2half_rn(src[i]);
}

__global__ void xcvt(const float* __restrict__ x) {
    size_t i = (size_t)blockIdx.x * 256 + threadIdx.x;
    int m = (int)(i >> 10), k = (int)(i & (H - 1));
    int t = m >> 6, b = m & 63;
    g_X16[i] = __float2half_rn(x[((size_t)b * T + t) * H + k]);
}

__global__ void init_states() {      // <<<RP, H>>>
    int r = blockIdx.x, j = threadIdx.x;
    float v = (r < R) ? g_traj[r & 7][j] : 0.f;
    __half hv16 = __float2half_rn(v);
    size_t o = (size_t)r * H + j;
    g_h1[0][o] = v;  g_h1[1][o] = v;
    g_h2[0][o] = v;  g_h2[1][o] = v;
#pragma unroll
    for (int s = 0; s < 4; s++) g_A16[(size_t)s * RP * H + o] = hv16;
}

// ================== HMMA fp16 core (A via .cg, W via .ca) =====================
__device__ __forceinline__ void mma_core(
    uint32_t sbase, int tid, int lane, int wm, int wn,
    const __half* A, const __half* W,
    int r0, int n0, int kbase, int nst, float acc[4][4][4]) {

    uint32_t aoff = (uint32_t)(wm + (lane & 15)) * 80 + ((lane >> 4) << 4);
    uint32_t woff = (uint32_t)(wn + ((lane >> 4) << 3) + (lane & 7)) * 80
                  + (((lane >> 3) & 1) << 4);

    {
        uint32_t sb2 = sbase;
#pragma unroll
        for (int j = 0; j < 2; j++) {
            int u = tid + j * 256;
            int row = u >> 2, kc = (u & 3) << 3;
            uint32_t doff = (uint32_t)row * 80 + ((uint32_t)kc << 1);
            cp16cg(sb2 + doff,      A + (size_t)(r0 + row) * H + kbase + kc);
            cp16ca(sb2 + TB + doff, W + (size_t)(n0 + row) * H + kbase + kc);
        }
        CPCOMMIT();
    }

    for (int st = 0; st < nst; st++) {
        if (st + 1 < nst) {
            int kg = kbase + (st + 1) * 32;
            uint32_t sb2 = sbase + ((st + 1) & 1) * SETB;
#pragma unroll
            for (int j = 0; j < 2; j++) {
                int u = tid + j * 256;
                int row = u >> 2, kc = (u & 3) << 3;
                uint32_t doff = (uint32_t)row * 80 + ((uint32_t)kc << 1);
                cp16cg(sb2 + doff,      A + (size_t)(r0 + row) * H + kg + kc);
                cp16ca(sb2 + TB + doff, W + (size_t)(n0 + row) * H + kg + kc);
            }
            CPCOMMIT();
            CPWAIT1();
        } else {
            CPWAIT0();
        }
        __syncthreads();

        uint32_t bs = sbase + (st & 1) * SETB;
        uint32_t uA = bs, uW = bs + TB;
#pragma unroll
        for (int kh = 0; kh < 2; kh++) {
            unsigned af[4][4], wf[2][4];
            uint32_t ko = (uint32_t)kh << 5;
#pragma unroll
            for (int mt = 0; mt < 4; mt++)
                ldsm4(af[mt], uA + aoff + mt * 1280 + ko);
#pragma unroll
            for (int p = 0; p < 2; p++)
                ldsm4(wf[p], uW + woff + p * 1280 + ko);
#pragma unroll
            for (int mt = 0; mt < 4; mt++)
#pragma unroll
                for (int nt = 0; nt < 4; nt++)
                    mma16816(acc[mt][nt], af[mt], &wf[nt >> 1][(nt & 1) * 2]);
        }
        __syncthreads();
    }
}

__device__ __forceinline__ void mma_epi(float* P, int r0, int n0, int kz,
                                        int wm, int wn, int lane,
                                        float acc[4][4][4]) {
    size_t pb = (size_t)kz * ((size_t)RP * G3);
#pragma unroll
    for (int mt = 0; mt < 4; mt++) {
        int row = r0 + wm + mt * 16 + (lane >> 2);
#pragma unroll
        for (int nt = 0; nt < 4; nt++) {
            int col = n0 + wn + nt * 8 + (lane & 3) * 2;
            float2 v0 = {acc[mt][nt][0], acc[mt][nt][1]};
            float2 v1 = {acc[mt][nt][2], acc[mt][nt][3]};
            *(float2*)&P[pb + (size_t)row * G3 + col] = v0;
            *(float2*)&P[pb + (size_t)(row + 8) * G3 + col] = v1;
        }
    }
}

// ================== gi0 GEMM ==================================================
__global__ void __launch_bounds__(256, 2) gi0_mma(const float* __restrict__ bi0) {
    extern __shared__ __align__(16) char dynsm[];
    uint32_t sbase = smem_u32(dynsm);
    int tid = threadIdx.x, wid = tid >> 5, lane = tid & 31;
    const __half* W = g_W16 + 3ull * G3 * H;

    int r0 = blockIdx.x * BM, n0 = blockIdx.y * BN;
    int wm = (wid >> 2) * 64, wn = (wid & 3) * 32;

    float acc[4][4][4] = {};
    mma_core(sbase, tid, lane, wm, wn, g_X16, W, r0, n0, 0, H / 32, acc);

#pragma unroll
    for (int mt = 0; mt < 4; mt++) {
        int row = r0 + wm + mt * 16 + (lane >> 2);
#pragma unroll
        for (int nt = 0; nt < 4; nt++) {
            int col = n0 + wn + nt * 8 + (lane & 3) * 2;
            float b0 = bi0[col], b1 = bi0[col + 1];
            float2 v0 = {acc[mt][nt][0] + b0, acc[mt][nt][1] + b1};
            float2 v1 = {acc[mt][nt][2] + b0, acc[mt][nt][3] + b1};
            *(float2*)&g_gi0[(size_t)row * G3 + col] = v0;
            *(float2*)&g_gi0[(size_t)(row + 8) * G3 + col] = v1;
        }
    }
}

// ---------------- finalizer device functions ----------------------------------
__device__ __forceinline__ void st_hv(int slot, size_t o, const float* hv,
                                      float* hbuf) {
    *(float4*)&hbuf[o] = make_float4(hv[0], hv[1], hv[2], hv[3]);
    __half h16[4];
#pragma unroll
    for (int v = 0; v < 4; v++) h16[v] = __float2half_rn(hv[v]);
    *(uint2*)&g_A16[(size_t)slot * RP * H + o] = *(const uint2*)h16;
}

__device__ __forceinline__ void l0fin_dev(int blk, int tid,
                                          const float* __restrict__ bh0,
                                          int step, int src) {
    int e = (blk * 256 + tid) << 2;
    int r = e >> 10, j = e & 1023;
    size_t base = (size_t)r * G3 + j;
    float acc[3][4] = {};
#pragma unroll
    for (int ks = 0; ks < KS; ks++) {
        const float* p = g_P0 + (size_t)ks * ((size_t)RP * G3) + base;
#pragma unroll
        for (int g = 0; g < 3; g++) {
            float4 v = __ldcg((const float4*)(p + (size_t)g * H));
            acc[g][0] += v.x; acc[g][1] += v.y; acc[g][2] += v.z; acc[g][3] += v.w;
        }
    }
    const float* gi = g_gi0 + ((size_t)((r >> 3) * SEQ + step)) * G3 + j;
    float4 gr = *(const float4*)gi;
    float4 gz = *(const float4*)(gi + H);
    float4 gn = *(const float4*)(gi + 2 * H);
    float4 br = *(const float4*)(bh0 + j);
    float4 bz = *(const float4*)(bh0 + H + j);
    float4 bn = *(const float4*)(bh0 + 2 * H + j);
    size_t o = (size_t)r * H + j;
    float4 hp = __ldcg((const float4*)&g_h1[src][o]);
    float grv[4] = {gr.x, gr.y, gr.z, gr.w}, gzv[4] = {gz.x, gz.y, gz.z, gz.w};
    float gnv[4] = {gn.x, gn.y, gn.z, gn.w}, brv[4] = {br.x, br.y, br.z, br.w};
    float bzv[4] = {bz.x, bz.y, bz.z, bz.w}, bnv[4] = {bn.x, bn.y, bn.z, bn.w};
    float hpv[4] = {hp.x, hp.y, hp.z, hp.w}, hv[4];
#pragma unroll
    for (int v = 0; v < 4; v++) {
        float rg = sigf(grv[v] + acc[0][v] + brv[v]);
        float z  = sigf(gzv[v] + acc[1][v] + bzv[v]);
        float n  = tanhf(gnv[v] + rg * (acc[2][v] + bnv[v]));
        hv[v] = (1.f - z) * n + z * hpv[v];
    }
    int dst = src ^ 1;
    st_hv(dst, o, hv, g_h1[dst]);
}

__device__ __forceinline__ void l1fin_dev(int blk, int tid,
                                          const float* __restrict__ bi1,
                                          const float* __restrict__ bh1,
                                          float* __restrict__ out,
                                          int step, int src) {
    int e = (blk * 256 + tid) << 2;
    int r = e >> 10, j = e & 1023;
    size_t base = (size_t)r * G3 + j;
    float ai[3][4] = {}, ah[3][4] = {};
#pragma unroll
    for (int ks = 0; ks < KS; ks++) {
        const float* pi = g_PI + (size_t)ks * ((size_t)RP * G3) + base;
        const float* ph = g_PH + (size_t)ks * ((size_t)RP * G3) + base;
#pragma unroll
        for (int g = 0; g < 3; g++) {
            float4 vi = __ldcg((const float4*)(pi + (size_t)g * H));
            float4 vh = __ldcg((const float4*)(ph + (size_t)g * H));
            ai[g][0] += vi.x; ai[g][1] += vi.y; ai[g][2] += vi.z; ai[g][3] += vi.w;
            ah[g][0] += vh.x; ah[g][1] += vh.y; ah[g][2] += vh.z; ah[g][3] += vh.w;
        }
    }
    float4 bir = *(const float4*)(bi1 + j);
    float4 biz = *(const float4*)(bi1 + H + j);
    float4 bin = *(const float4*)(bi1 + 2 * H + j);
    float4 bhr = *(const float4*)(bh1 + j);
    float4 bhz = *(const float4*)(bh1 + H + j);
    float4 bhn = *(const float4*)(bh1 + 2 * H + j);
    size_t o = (size_t)r * H + j;
    float4 hp = __ldcg((const float4*)&g_h2[src][o]);
    float birv[4] = {bir.x, bir.y, bir.z, bir.w}, bizv[4] = {biz.x, biz.y, biz.z, biz.w};
    float binv[4] = {bin.x, bin.y, bin.z, bin.w}, bhrv[4] = {bhr.x, bhr.y, bhr.z, bhr.w};
    float bhzv[4] = {bhz.x, bhz.y, bhz.z, bhz.w}, bhnv[4] = {bhn.x, bhn.y, bhn.z, bhn.w};
    float hpv[4] = {hp.x, hp.y, hp.z, hp.w}, hv[4];
#pragma unroll
    for (int v = 0; v < 4; v++) {
        float rg = sigf(ai[0][v] + birv[v] + ah[0][v] + bhrv[v]);
        float z  = sigf(ai[1][v] + bizv[v] + ah[1][v] + bhzv[v]);
        float n  = tanhf(ai[2][v] + binv[v] + rg * (ah[2][v] + bhnv[v]));
        hv[v] = (1.f - z) * n + z * hpv[v];
    }
    int dst = src ^ 1;
    st_hv(2 + dst, o, hv, g_h2[dst]);
    *(float4*)&out[((size_t)step * R + r) * H + j] =
        make_float4(hv[0], hv[1], hv[2], hv[3]);
}

// ================== persistent GRU step kernel ================================
__global__ void __launch_bounds__(256, 2) gru_steps(
    const float* __restrict__ bh0, const float* __restrict__ bi1,
    const float* __restrict__ bh1, float* __restrict__ out) {
    extern __shared__ __align__(16) char dynsm[];
    uint32_t sbase = smem_u32(dynsm);
    __shared__ unsigned sgen;
    int tid = threadIdx.x, wid = tid >> 5, lane = tid & 31;
    int cta = blockIdx.x;
    int grp = cta / 18;                    // 16 groups of 18
    int wm = (wid >> 2) * 64, wn = (wid & 3) * 32;

    if (tid == 0) sgen = *(volatile unsigned*)&g_gen2;
    __syncthreads();
    unsigned base = sgen, bi = 0;

    // ---- prologue: gh0(0) (96 jobs) ----
    if (cta < 96) {
        int x = cta & 1, y = (cta >> 1) % 24, kz = cta / 48;
        float acc[4][4][4] = {};
        mma_core(sbase, tid, lane, wm, wn, g_A16, g_W16,
                 x * BM, y * BN, kz * KC, KC / 32, acc);
        mma_epi(g_P0, x * BM, y * BN, kz, wm, wn, lane, acc);
    }
    tbar(g_leafB, &g_rootB, &g_gen2, grp, 18, 16, base, ++bi);

    for (int u = cta; u < 240; u += SNB) l0fin_dev(u, tid, bh0, 0, 0);
    tbar(g_leafB, &g_rootB, &g_gen2, grp, 18, 16, base, ++bi);

    // ---- 64 steps ----
    for (int s = 0; s < SEQ; s++) {
        int src = s & 1;
        int njobs = (s == SEQ - 1) ? 192 : 288;
        if (cta < njobs) {
            int x = cta & 1, y = (cta >> 1) % 24, z = cta / 48;
            int prob = z >> 1, kz = z & 1;
            int asel = (prob == 1) ? (2 + src) : (src ^ 1);
            int wsel = (prob == 0) ? 1 : (prob == 1) ? 2 : 0;
            float* P = (prob == 0) ? g_PI : (prob == 1) ? g_PH : g_P0;
            const __half* A = g_A16 + (size_t)asel * RP * H;
            const __half* W = g_W16 + (size_t)wsel * G3 * H;
            float acc[4][4][4] = {};
            mma_core(sbase, tid, lane, wm, wn, A, W,
                     x * BM, y * BN, kz * KC, KC / 32, acc);
            mma_epi(P, x * BM, y * BN, kz, wm, wn, lane, acc);
        }
        tbar(g_leafB, &g_rootB, &g_gen2, grp, 18, 16, base, ++bi);

        int fj = (s == SEQ - 1) ? 240 : 480;
        for (int u = cta; u < fj; u += SNB) {
            if (u < 240) l1fin_dev(u, tid, bi1, bh1, out, s, src);
            else         l0fin_dev(u - 240, tid, bh0, s + 1, src ^ 1);
        }
        tbar(g_leafB, &g_rootB, &g_gen2, grp, 18, 16, base, ++bi);
    }
}

// ---------------- launcher --------------------------------------------------
extern "C" void kernel_launch(void* const* d_in, const int* in_sizes, int n_in,
                              void* d_out, int out_size) {
    const float* x   = (const float*)d_in[0];
    const float* w1  = (const float*)d_in[1];
    const float* b1  = (const float*)d_in[2];
    const float* w2  = (const float*)d_in[3];
    const float* b2  = (const float*)d_in[4];
    const float* w3  = (const float*)d_in[5];
    const float* b3  = (const float*)d_in[6];
    const float* wi0 = (const float*)d_in[7];
    const float* wh0 = (const float*)d_in[8];
    const float* bi0 = (const float*)d_in[9];
    const float* bh0 = (const float*)d_in[10];
    const float* wi1 = (const float*)d_in[11];
    const float* wh1 = (const float*)d_in[12];
    const float* bi1 = (const float*)d_in[13];
    const float* bh1 = (const float*)d_in[14];
    float* out = (float*)d_out;

    static int s_init = 0;
    if (!s_init) {
        cudaFuncSetAttribute(gi0_mma,   cudaFuncAttributeMaxDynamicSharedMemorySize, DSM);
        cudaFuncSetAttribute(gru_steps, cudaFuncAttributeMaxDynamicSharedMemorySize, DSM);
        s_init = 1;
    }

    wcvt4<<<dim3((G3 * H) / 256, 4), 256>>>(wh0, wi1, wh1, wi0);
    xcvt<<<(MX * H) / 256, 256>>>(x);

    gi0_mma<<<dim3(MX / BM, G3 / BN), 256, DSM>>>(bi0);
    ode_all<<<NB, 256>>>(w1, b1, w2, b2, w3, b3);
    init_states<<<RP, H>>>();

    gru_steps<<<SNB, 256, DSM>>>(bh0, bi1, bh1, out);
}

// round 15
// speedup vs baseline: 1.1570x; 1.1570x over previous
#include <cuda_runtime.h>
#include <cuda_fp16.h>
#include <cstdint>
#include <cstddef>

#define H    1024
#define FF   2048
#define G3   3072
#define SEQ  64
#define T    30
#define NSEG 8
#define SUB  4
#define R    240
#define RP   256
#define DT   (1.0f/32.0f)
#define NB   128
#define NWARP (NB*8)
#define SNB  288
#define KS   2
#define KC   512
#define BM   128
#define BN   128
#define BK   64
#define MX   (T*SEQ)

// smem tile: 128 rows x (64 halves = 128B + 16B pad) = 144B stride
#define RS   144
#define TB   (128*RS)       // 18432
#define SETB (2*TB)         // 36864
#define DSM  (2*SETB)       // 73728

typedef unsigned long long ull;

// ---------------- scratch ----------------------------------------------------
__device__ float g_h[H], g_heff[H], g_t1[FF], g_t2[FF];
__device__ float g_traj[NSEG][H];
__device__ __align__(16) float g_gi0[(size_t)MX * G3];
__device__ __align__(16) float g_h1[2][RP * H];
__device__ __align__(16) float g_h2[2][RP * H];
__device__ __align__(16) float g_P0[(size_t)KS * RP * G3];
__device__ __align__(16) float g_PI[(size_t)KS * RP * G3];
__device__ __align__(16) float g_PH[(size_t)KS * RP * G3];
__device__ __align__(16) __half g_W16[4ull * G3 * H];   // wh0, wi1, wh1, wi0
__device__ __align__(16) __half g_A16[4ull * RP * H];   // h1[0],h1[1],h2[0],h2[1]
__device__ __align__(16) __half g_X16[(size_t)MX * H];
__device__ unsigned g_cnt,  g_gen;    // ODE barrier (flat)
__device__ unsigned g_cnt2, g_gen2;   // step barrier (flat)

__device__ __forceinline__ float sigf(float v) { return 1.f / (1.f + expf(-v)); }

// ---- mma / async helpers ----------------------------------------------------
__device__ __forceinline__ uint32_t smem_u32(const void* p) {
    uint32_t a;
    asm("{ .reg .u64 t; cvta.to.shared.u64 t, %1; cvt.u32.u64 %0, t; }"
        : "=r"(a) : "l"(p));
    return a;
}
__device__ __forceinline__ void ldsm4(unsigned* r, uint32_t addr) {
    asm volatile("ldmatrix.sync.aligned.m8n8.x4.shared.b16 {%0,%1,%2,%3},[%4];"
                 : "=r"(r[0]), "=r"(r[1]), "=r"(r[2]), "=r"(r[3]) : "r"(addr));
}
__device__ __forceinline__ void mma16816(float* c, const unsigned* a,
                                         const unsigned* b) {
    asm volatile(
        "mma.sync.aligned.m16n8k16.row.col.f32.f16.f16.f32 "
        "{%0,%1,%2,%3},{%4,%5,%6,%7},{%8,%9},{%0,%1,%2,%3};"
        : "+f"(c[0]), "+f"(c[1]), "+f"(c[2]), "+f"(c[3])
        : "r"(a[0]), "r"(a[1]), "r"(a[2]), "r"(a[3]), "r"(b[0]), "r"(b[1]));
}
__device__ __forceinline__ void cp16ca(uint32_t dst, const void* src) {
    asm volatile("cp.async.ca.shared.global.L2::128B [%0],[%1],16;"
                 :: "r"(dst), "l"(src));
}
__device__ __forceinline__ void cp16cg(uint32_t dst, const void* src) {
    asm volatile("cp.async.cg.shared.global.L2::128B [%0],[%1],16;"
                 :: "r"(dst), "l"(src));
}
#define CPCOMMIT() asm volatile("cp.async.commit_group;" ::: "memory")
#define CPWAIT1()  asm volatile("cp.async.wait_group 1;" ::: "memory")
#define CPWAIT0()  asm volatile("cp.async.wait_group 0;" ::: "memory")

// ---- flat acq_rel global barrier (R12-proven) --------------------------------
__device__ __forceinline__ void gbar2(unsigned* cnt, unsigned* gen, unsigned nb,
                                      unsigned base, unsigned idx) {
    __syncthreads();
    if (threadIdx.x == 0) {
        unsigned old;
        asm volatile("atom.acq_rel.gpu.global.add.u32 %0, [%1], 1;"
                     : "=r"(old) : "l"(cnt) : "memory");
        if (old == nb - 1) {
            asm volatile("st.relaxed.gpu.global.u32 [%0], 0;"
                         :: "l"(cnt) : "memory");
            unsigned d;
            asm volatile("atom.release.gpu.global.add.u32 %0, [%1], 1;"
                         : "=r"(d) : "l"(gen) : "memory");
        } else {
            unsigned g;
            do {
                asm volatile("ld.acquire.gpu.global.u32 %0, [%1];"
                             : "=r"(g) : "l"(gen) : "memory");
            } while ((g - base) < idx);
        }
    }
    __syncthreads();
}

// =================== persistent ODE kernel (fp32 weights, R12) ==============
__device__ __forceinline__ float2 rowdot2(const float* __restrict__ w0,
                                          const float* __restrict__ w1,
                                          const float* __restrict__ sv,
                                          int K, int lane) {
    float s0 = 0.f, s1 = 0.f;
#pragma unroll 4
    for (int k = lane * 4; k < K; k += 128) {
        float4 a = *(const float4*)(w0 + k);
        float4 b = *(const float4*)(w1 + k);
        float4 v = *(const float4*)(sv + k);
        s0 += a.x * v.x + a.y * v.y + a.z * v.z + a.w * v.w;
        s1 += b.x * v.x + b.y * v.y + b.z * v.z + b.w * v.w;
    }
#pragma unroll
    for (int o = 16; o; o >>= 1) {
        s0 += __shfl_xor_sync(0xffffffffu, s0, o);
        s1 += __shfl_xor_sync(0xffffffffu, s1, o);
    }
    return make_float2(s0, s1);
}

__device__ __forceinline__ float rowdot(const float* __restrict__ wr,
                                        const float* __restrict__ sv,
                                        int K, int lane) {
    float s = 0.f;
#pragma unroll 8
    for (int k = lane * 4; k < K; k += 128) {
        float4 w = *(const float4*)(wr + k);
        float4 v = *(const float4*)(sv + k);
        s += w.x * v.x + w.y * v.y + w.z * v.z + w.w * v.w;
    }
#pragma unroll
    for (int o = 16; o; o >>= 1) s += __shfl_xor_sync(0xffffffffu, s, o);
    return s;
}

__global__ void __launch_bounds__(256, 1) ode_all(
    const float* __restrict__ w1, const float* __restrict__ b1,
    const float* __restrict__ w2, const float* __restrict__ b2,
    const float* __restrict__ w3, const float* __restrict__ b3) {
    __shared__ __align__(16) float sv[FF];
    __shared__ unsigned sbase;
    int tid = threadIdx.x, lane = tid & 31, warp = tid >> 5;
    int wg = blockIdx.x * 8 + warp;

    if (tid == 0) sbase = *(volatile unsigned*)&g_gen;
    if (blockIdx.x == 0)
        for (int i = tid; i < H; i += 256) __stcg(&g_h[i], 0.f);
    __syncthreads();
    unsigned base = sbase, bi = 0;
    gbar2(&g_cnt, &g_gen, NB, base, ++bi);

    float hreg = 0.f, ks = 0.f;

    for (int iv = 0; iv < NSEG; iv++)
    for (int sb = 0; sb < SUB; sb++)
    for (int m = 0; m < 4; m++) {
        const float* vsrc = (m == 0) ? g_h : g_heff;
        for (int i = tid; i < H; i += 256) sv[i] = __ldcg(vsrc + i);
        __syncthreads();
        {   // stage 1
            float2 s = rowdot2(w1 + (size_t)wg * H,
                               w1 + (size_t)(wg + NWARP) * H, sv, H, lane);
            if (lane == 0) {
                __stcg(&g_t1[wg],         tanhf(s.x + b1[wg]));
                __stcg(&g_t1[wg + NWARP], tanhf(s.y + b1[wg + NWARP]));
            }
        }
        gbar2(&g_cnt, &g_gen, NB, base, ++bi);

        for (int i = tid; i < FF; i += 256) sv[i] = __ldcg(&g_t1[i]);
        __syncthreads();
        {   // stage 2
            float2 s = rowdot2(w2 + (size_t)wg * FF,
                               w2 + (size_t)(wg + NWARP) * FF, sv, FF, lane);
            if (lane == 0) {
                __stcg(&g_t2[wg],         tanhf(s.x + b2[wg]));
                __stcg(&g_t2[wg + NWARP], tanhf(s.y + b2[wg + NWARP]));
            }
        }
        gbar2(&g_cnt, &g_gen, NB, base, ++bi);

        for (int i = tid; i < FF; i += 256) sv[i] = __ldcg(&g_t2[i]);
        __syncthreads();
        if (wg < H) {   // stage 3 + RK4 combine
            float s = rowdot(w3 + (size_t)wg * FF, sv, FF, lane);
            if (lane == 0) {
                float kv = s + b3[wg];
                if (m == 0)      { ks = kv;          __stcg(&g_heff[wg], hreg + 0.5f * DT * kv); }
                else if (m == 1) { ks += 2.f * kv;   __stcg(&g_heff[wg], hreg + 0.5f * DT * kv); }
                else if (m == 2) { ks += 2.f * kv;   __stcg(&g_heff[wg], hreg + DT * kv); }
                else {
                    hreg += (DT / 6.f) * (ks + kv);
                    __stcg(&g_h[wg], hreg);
                    if (sb == SUB - 1) g_traj[iv][wg] = hreg;
                }
            }
        }
        gbar2(&g_cnt, &g_gen, NB, base, ++bi);
    }
}

// ---------------- fp16 conversions -------------------------------------------
__global__ void wcvt4(const float* __restrict__ w0, const float* __restrict__ w1,
                      const float* __restrict__ w2, const float* __restrict__ w3) {
    int m = blockIdx.y;
    const float* src = (m == 0) ? w0 : (m == 1) ? w1 : (m == 2) ? w2 : w3;
    size_t i = (size_t)blockIdx.x * 256 + threadIdx.x;
    g_W16[(size_t)m * G3 * H + i] = __float2half_rn(src[i]);
}

__global__ void xcvt(const float* __restrict__ x) {
    size_t i = (size_t)blockIdx.x * 256 + threadIdx.x;
    int m = (int)(i >> 10), k = (int)(i & (H - 1));
    int t = m >> 6, b = m & 63;
    g_X16[i] = __float2half_rn(x[((size_t)b * T + t) * H + k]);
}

__global__ void init_states() {      // <<<RP, H>>>
    int r = blockIdx.x, j = threadIdx.x;
    float v = (r < R) ? g_traj[r & 7][j] : 0.f;
    __half hv16 = __float2half_rn(v);
    size_t o = (size_t)r * H + j;
    g_h1[0][o] = v;  g_h1[1][o] = v;
    g_h2[0][o] = v;  g_h2[1][o] = v;
#pragma unroll
    for (int s = 0; s < 4; s++) g_A16[(size_t)s * RP * H + o] = hv16;
}

// ================== HMMA fp16 core, BK=64 ====================================
__device__ __forceinline__ void mma_core(
    uint32_t sbase, int tid, int lane, int wm, int wn,
    const __half* A, const __half* W,
    int r0, int n0, int kbase, int nst, float acc[4][4][4]) {

    uint32_t aoff = (uint32_t)(wm + (lane & 15)) * RS + ((lane >> 4) << 4);
    uint32_t woff = (uint32_t)(wn + ((lane >> 4) << 3) + (lane & 7)) * RS
                  + (((lane >> 3) & 1) << 4);

    {
        uint32_t sb2 = sbase;
#pragma unroll
        for (int j = 0; j < 4; j++) {             // 1024 uint4 per tile
            int u = tid + j * 256;
            int row = u >> 3, kc = (u & 7) << 3;  // 8 uint4 (=64 halves) per row
            uint32_t doff = (uint32_t)row * RS + ((uint32_t)kc << 1);
            cp16cg(sb2 + doff,      A + (size_t)(r0 + row) * H + kbase + kc);
            cp16ca(sb2 + TB + doff, W + (size_t)(n0 + row) * H + kbase + kc);
        }
        CPCOMMIT();
    }

    for (int st = 0; st < nst; st++) {
        if (st + 1 < nst) {
            int kg = kbase + (st + 1) * BK;
            uint32_t sb2 = sbase + ((st + 1) & 1) * SETB;
#pragma unroll
            for (int j = 0; j < 4; j++) {
                int u = tid + j * 256;
                int row = u >> 3, kc = (u & 7) << 3;
                uint32_t doff = (uint32_t)row * RS + ((uint32_t)kc << 1);
                cp16cg(sb2 + doff,      A + (size_t)(r0 + row) * H + kg + kc);
                cp16ca(sb2 + TB + doff, W + (size_t)(n0 + row) * H + kg + kc);
            }
            CPCOMMIT();
            CPWAIT1();
        } else {
            CPWAIT0();
        }
        __syncthreads();

        uint32_t bs = sbase + (st & 1) * SETB;
        uint32_t uA = bs, uW = bs + TB;
#pragma unroll
        for (int kh = 0; kh < 4; kh++) {          // 4 k16 chunks per BK=64
            unsigned af[4][4], wf[2][4];
            uint32_t ko = (uint32_t)kh << 5;      // 16 halves = 32 B
#pragma unroll
            for (int mt = 0; mt < 4; mt++)
                ldsm4(af[mt], uA + aoff + mt * 16 * RS + ko);
#pragma unroll
            for (int p = 0; p < 2; p++)
                ldsm4(wf[p], uW + woff + p * 16 * RS + ko);
#pragma unroll
            for (int mt = 0; mt < 4; mt++)
#pragma unroll
                for (int nt = 0; nt < 4; nt++)
                    mma16816(acc[mt][nt], af[mt], &wf[nt >> 1][(nt & 1) * 2]);
        }
        __syncthreads();
    }
}

__device__ __forceinline__ void mma_epi(float* P, int r0, int n0, int kz,
                                        int wm, int wn, int lane,
                                        float acc[4][4][4]) {
    size_t pb = (size_t)kz * ((size_t)RP * G3);
#pragma unroll
    for (int mt = 0; mt < 4; mt++) {
        int row = r0 + wm + mt * 16 + (lane >> 2);
#pragma unroll
        for (int nt = 0; nt < 4; nt++) {
            int col = n0 + wn + nt * 8 + (lane & 3) * 2;
            float2 v0 = {acc[mt][nt][0], acc[mt][nt][1]};
            float2 v1 = {acc[mt][nt][2], acc[mt][nt][3]};
            *(float2*)&P[pb + (size_t)row * G3 + col] = v0;
            *(float2*)&P[pb + (size_t)(row + 8) * G3 + col] = v1;
        }
    }
}

// ================== gi0 GEMM ==================================================
__global__ void __launch_bounds__(256, 2) gi0_mma(const float* __restrict__ bi0) {
    extern __shared__ __align__(16) char dynsm[];
    uint32_t sbase = smem_u32(dynsm);
    int tid = threadIdx.x, wid = tid >> 5, lane = tid & 31;
    const __half* W = g_W16 + 3ull * G3 * H;

    int r0 = blockIdx.x * BM, n0 = blockIdx.y * BN;
    int wm = (wid >> 2) * 64, wn = (wid & 3) * 32;

    float acc[4][4][4] = {};
    mma_core(sbase, tid, lane, wm, wn, g_X16, W, r0, n0, 0, H / BK, acc);

#pragma unroll
    for (int mt = 0; mt < 4; mt++) {
        int row = r0 + wm + mt * 16 + (lane >> 2);
#pragma unroll
        for (int nt = 0; nt < 4; nt++) {
            int col = n0 + wn + nt * 8 + (lane & 3) * 2;
            float b0 = bi0[col], b1 = bi0[col + 1];
            float2 v0 = {acc[mt][nt][0] + b0, acc[mt][nt][1] + b1};
            float2 v1 = {acc[mt][nt][2] + b0, acc[mt][nt][3] + b1};
            *(float2*)&g_gi0[(size_t)row * G3 + col] = v0;
            *(float2*)&g_gi0[(size_t)(row + 8) * G3 + col] = v1;
        }
    }
}

// ---------------- finalizer device functions ----------------------------------
__device__ __forceinline__ void st_hv(int slot, size_t o, const float* hv,
                                      float* hbuf) {
    *(float4*)&hbuf[o] = make_float4(hv[0], hv[1], hv[2], hv[3]);
    __half h16[4];
#pragma unroll
    for (int v = 0; v < 4; v++) h16[v] = __float2half_rn(hv[v]);
    *(uint2*)&g_A16[(size_t)slot * RP * H + o] = *(const uint2*)h16;
}

__device__ __forceinline__ void l0fin_dev(int blk, int tid,
                                          const float* __restrict__ bh0,
                                          int step, int src) {
    int e = (blk * 256 + tid) << 2;
    int r = e >> 10, j = e & 1023;
    size_t base = (size_t)r * G3 + j;
    float acc[3][4] = {};
#pragma unroll
    for (int ks = 0; ks < KS; ks++) {
        const float* p = g_P0 + (size_t)ks * ((size_t)RP * G3) + base;
#pragma unroll
        for (int g = 0; g < 3; g++) {
            float4 v = __ldcg((const float4*)(p + (size_t)g * H));
            acc[g][0] += v.x; acc[g][1] += v.y; acc[g][2] += v.z; acc[g][3] += v.w;
        }
    }
    const float* gi = g_gi0 + ((size_t)((r >> 3) * SEQ + step)) * G3 + j;
    float4 gr = *(const float4*)gi;
    float4 gz = *(const float4*)(gi + H);
    float4 gn = *(const float4*)(gi + 2 * H);
    float4 br = *(const float4*)(bh0 + j);
    float4 bz = *(const float4*)(bh0 + H + j);
    float4 bn = *(const float4*)(bh0 + 2 * H + j);
    size_t o = (size_t)r * H + j;
    float4 hp = __ldcg((const float4*)&g_h1[src][o]);
    float grv[4] = {gr.x, gr.y, gr.z, gr.w}, gzv[4] = {gz.x, gz.y, gz.z, gz.w};
    float gnv[4] = {gn.x, gn.y, gn.z, gn.w}, brv[4] = {br.x, br.y, br.z, br.w};
    float bzv[4] = {bz.x, bz.y, bz.z, bz.w}, bnv[4] = {bn.x, bn.y, bn.z, bn.w};
    float hpv[4] = {hp.x, hp.y, hp.z, hp.w}, hv[4];
#pragma unroll
    for (int v = 0; v < 4; v++) {
        float rg = sigf(grv[v] + acc[0][v] + brv[v]);
        float z  = sigf(gzv[v] + acc[1][v] + bzv[v]);
        float n  = tanhf(gnv[v] + rg * (acc[2][v] + bnv[v]));
        hv[v] = (1.f - z) * n + z * hpv[v];
    }
    int dst = src ^ 1;
    st_hv(dst, o, hv, g_h1[dst]);
}

__device__ __forceinline__ void l1fin_dev(int blk, int tid,
                                          const float* __restrict__ bi1,
                                          const float* __restrict__ bh1,
                                          float* __restrict__ out,
                                          int step, int src) {
    int e = (blk * 256 + tid) << 2;
    int r = e >> 10, j = e & 1023;
    size_t base = (size_t)r * G3 + j;
    float ai[3][4] = {}, ah[3][4] = {};
#pragma unroll
    for (int ks = 0; ks < KS; ks++) {
        const float* pi = g_PI + (size_t)ks * ((size_t)RP * G3) + base;
        const float* ph = g_PH + (size_t)ks * ((size_t)RP * G3) + base;
#pragma unroll
        for (int g = 0; g < 3; g++) {
            float4 vi = __ldcg((const float4*)(pi + (size_t)g * H));
            float4 vh = __ldcg((const float4*)(ph + (size_t)g * H));
            ai[g][0] += vi.x; ai[g][1] += vi.y; ai[g][2] += vi.z; ai[g][3] += vi.w;
            ah[g][0] += vh.x; ah[g][1] += vh.y; ah[g][2] += vh.z; ah[g][3] += vh.w;
        }
    }
    float4 bir = *(const float4*)(bi1 + j);
    float4 biz = *(const float4*)(bi1 + H + j);
    float4 bin = *(const float4*)(bi1 + 2 * H + j);
    float4 bhr = *(const float4*)(bh1 + j);
    float4 bhz = *(const float4*)(bh1 + H + j);
    float4 bhn = *(const float4*)(bh1 + 2 * H + j);
    size_t o = (size_t)r * H + j;
    float4 hp = __ldcg((const float4*)&g_h2[src][o]);
    float birv[4] = {bir.x, bir.y, bir.z, bir.w}, bizv[4] = {biz.x, biz.y, biz.z, biz.w};
    float binv[4] = {bin.x, bin.y, bin.z, bin.w}, bhrv[4] = {bhr.x, bhr.y, bhr.z, bhr.w};
    float bhzv[4] = {bhz.x, bhz.y, bhz.z, bhz.w}, bhnv[4] = {bhn.x, bhn.y, bhn.z, bhn.w};
    float hpv[4] = {hp.x, hp.y, hp.z, hp.w}, hv[4];
#pragma unroll
    for (int v = 0; v < 4; v++) {
        float rg = sigf(ai[0][v] + birv[v] + ah[0][v] + bhrv[v]);
        float z  = sigf(ai[1][v] + bizv[v] + ah[1][v] + bhzv[v]);
        float n  = tanhf(ai[2][v] + binv[v] + rg * (ah[2][v] + bhnv[v]));
        hv[v] = (1.f - z) * n + z * hpv[v];
    }
    int dst = src ^ 1;
    st_hv(2 + dst, o, hv, g_h2[dst]);
    *(float4*)&out[((size_t)step * R + r) * H + j] =
        make_float4(hv[0], hv[1], hv[2], hv[3]);
}

// ================== persistent GRU step kernel ================================
__global__ void __launch_bounds__(256, 2) gru_steps(
    const float* __restrict__ bh0, const float* __restrict__ bi1,
    const float* __restrict__ bh1, float* __restrict__ out) {
    extern __shared__ __align__(16) char dynsm[];
    uint32_t sbase = smem_u32(dynsm);
    __shared__ unsigned sgen;
    int tid = threadIdx.x, wid = tid >> 5, lane = tid & 31;
    int cta = blockIdx.x;
    int wm = (wid >> 2) * 64, wn = (wid & 3) * 32;

    if (tid == 0) sgen = *(volatile unsigned*)&g_gen2;
    __syncthreads();
    unsigned base = sgen, bi = 0;

    // ---- prologue: gh0(0) (96 jobs) ----
    if (cta < 96) {
        int x = cta & 1, y = (cta >> 1) % 24, kz = cta / 48;
        float acc[4][4][4] = {};
        mma_core(sbase, tid, lane, wm, wn, g_A16, g_W16,
                 x * BM, y * BN, kz * KC, KC / BK, acc);
        mma_epi(g_P0, x * BM, y * BN, kz, wm, wn, lane, acc);
    }
    gbar2(&g_cnt2, &g_gen2, SNB, base, ++bi);

    for (int u = cta; u < 240; u += SNB) l0fin_dev(u, tid, bh0, 0, 0);
    gbar2(&g_cnt2, &g_gen2, SNB, base, ++bi);

    // ---- 64 steps ----
    for (int s = 0; s < SEQ; s++) {
        int src = s & 1;
        int njobs = (s == SEQ - 1) ? 192 : 288;
        if (cta < njobs) {
            int x = cta & 1, y = (cta >> 1) % 24, z = cta / 48;
            int prob = z >> 1, kz = z & 1;
            int asel = (prob == 1) ? (2 + src) : (src ^ 1);
            int wsel = (prob == 0) ? 1 : (prob == 1) ? 2 : 0;
            float* P = (prob == 0) ? g_PI : (prob == 1) ? g_PH : g_P0;
            const __half* A = g_A16 + (size_t)asel * RP * H;
            const __half* W = g_W16 + (size_t)wsel * G3 * H;
            float acc[4][4][4] = {};
            mma_core(sbase, tid, lane, wm, wn, A, W,
                     x * BM, y * BN, kz * KC, KC / BK, acc);
            mma_epi(P, x * BM, y * BN, kz, wm, wn, lane, acc);
        }
        gbar2(&g_cnt2, &g_gen2, SNB, base, ++bi);

        int fj = (s == SEQ - 1) ? 240 : 480;
        for (int u = cta; u < fj; u += SNB) {
            if (u < 240) l1fin_dev(u, tid, bi1, bh1, out, s, src);
            else         l0fin_dev(u - 240, tid, bh0, s + 1, src ^ 1);
        }
        gbar2(&g_cnt2, &g_gen2, SNB, base, ++bi);
    }
}

// ---------------- launcher --------------------------------------------------
extern "C" void kernel_launch(void* const* d_in, const int* in_sizes, int n_in,
                              void* d_out, int out_size) {
    const float* x   = (const float*)d_in[0];
    const float* w1  = (const float*)d_in[1];
    const float* b1  = (const float*)d_in[2];
    const float* w2  = (const float*)d_in[3];
    const float* b2  = (const float*)d_in[4];
    const float* w3  = (const float*)d_in[5];
    const float* b3  = (const float*)d_in[6];
    const float* wi0 = (const float*)d_in[7];
    const float* wh0 = (const float*)d_in[8];
    const float* bi0 = (const float*)d_in[9];
    const float* bh0 = (const float*)d_in[10];
    const float* wi1 = (const float*)d_in[11];
    const float* wh1 = (const float*)d_in[12];
    const float* bi1 = (const float*)d_in[13];
    const float* bh1 = (const float*)d_in[14];
    float* out = (float*)d_out;

    static int s_init = 0;
    if (!s_init) {
        cudaFuncSetAttribute(gi0_mma,   cudaFuncAttributeMaxDynamicSharedMemorySize, DSM);
        cudaFuncSetAttribute(gru_steps, cudaFuncAttributeMaxDynamicSharedMemorySize, DSM);
        s_init = 1;
    }

    wcvt4<<<dim3((G3 * H) / 256, 4), 256>>>(wh0, wi1, wh1, wi0);
    xcvt<<<(MX * H) / 256, 256>>>(x);

    gi0_mma<<<dim3(MX / BM, G3 / BN), 256, DSM>>>(bi0);
    ode_all<<<NB, 256>>>(w1, b1, w2, b2, w3, b3);
    init_states<<<RP, H>>>();

    gru_steps<<<SNB, 256, DSM>>>(bh0, bi1, bh1, out);
}

// round 16
// speedup vs baseline: 1.2007x; 1.0378x over previous
#include <cuda_runtime.h>
#include <cuda_fp16.h>
#include <cstdint>
#include <cstddef>

#define H    1024
#define FF   2048
#define G3   3072
#define SEQ  64
#define T    30
#define NSEG 8
#define SUB  4
#define R    240
#define RP   256
#define DT   (1.0f/32.0f)
#define NB   128
#define NWARP (NB*8)
#define SNB  288
#define KS   2
#define KC   512
#define BM   128
#define BN   128
#define BK   64
#define MX   (T*SEQ)

// smem tile: 128 rows x (64 halves = 128B + 16B pad) = 144B stride
#define RS   144
#define TB   (128*RS)       // 18432
#define SETB (2*TB)         // 36864
#define DSM  (2*SETB)       // 73728

typedef unsigned long long ull;

// ---------------- scratch ----------------------------------------------------
__device__ float g_h[H], g_heff[H], g_t1[FF], g_t2[FF];
__device__ float g_traj[NSEG][H];
__device__ __align__(16) float g_gi0[(size_t)MX * G3];
__device__ __align__(16) float g_h1[2][RP * H];
__device__ __align__(16) float g_h2[2][RP * H];
__device__ __align__(16) float g_P0[(size_t)KS * RP * G3];
__device__ __align__(16) float g_PI[(size_t)KS * RP * G3];
__device__ __align__(16) float g_PH[(size_t)KS * RP * G3];
__device__ __align__(16) __half g_W16[4ull * G3 * H];   // wh0, wi1, wh1, wi0
__device__ __align__(16) __half g_A16[4ull * RP * H];   // h1[0],h1[1],h2[0],h2[1]
__device__ __align__(16) __half g_X16[(size_t)MX * H];
__device__ __align__(16) __half g_O16[8ull * 1024 * 1024]; // w1|w2|w3 fp16
#define O_W1 0
#define O_W2 (2ull*1024*1024)
#define O_W3 (6ull*1024*1024)
__device__ unsigned g_cnt,  g_gen;    // ODE barrier (flat)
__device__ unsigned g_cnt2, g_gen2;   // step barrier (flat)

__device__ __forceinline__ float sigf(float v) { return 1.f / (1.f + expf(-v)); }

// ---- mma / async helpers ----------------------------------------------------
__device__ __forceinline__ uint32_t smem_u32(const void* p) {
    uint32_t a;
    asm("{ .reg .u64 t; cvta.to.shared.u64 t, %1; cvt.u32.u64 %0, t; }"
        : "=r"(a) : "l"(p));
    return a;
}
__device__ __forceinline__ void ldsm4(unsigned* r, uint32_t addr) {
    asm volatile("ldmatrix.sync.aligned.m8n8.x4.shared.b16 {%0,%1,%2,%3},[%4];"
                 : "=r"(r[0]), "=r"(r[1]), "=r"(r[2]), "=r"(r[3]) : "r"(addr));
}
__device__ __forceinline__ void mma16816(float* c, const unsigned* a,
                                         const unsigned* b) {
    asm volatile(
        "mma.sync.aligned.m16n8k16.row.col.f32.f16.f16.f32 "
        "{%0,%1,%2,%3},{%4,%5,%6,%7},{%8,%9},{%0,%1,%2,%3};"
        : "+f"(c[0]), "+f"(c[1]), "+f"(c[2]), "+f"(c[3])
        : "r"(a[0]), "r"(a[1]), "r"(a[2]), "r"(a[3]), "r"(b[0]), "r"(b[1]));
}
__device__ __forceinline__ void cp16ca(uint32_t dst, const void* src) {
    asm volatile("cp.async.ca.shared.global.L2::128B [%0],[%1],16;"
                 :: "r"(dst), "l"(src));
}
__device__ __forceinline__ void cp16cg(uint32_t dst, const void* src) {
    asm volatile("cp.async.cg.shared.global.L2::128B [%0],[%1],16;"
                 :: "r"(dst), "l"(src));
}
#define CPCOMMIT() asm volatile("cp.async.commit_group;" ::: "memory")
#define CPWAIT1()  asm volatile("cp.async.wait_group 1;" ::: "memory")
#define CPWAIT0()  asm volatile("cp.async.wait_group 0;" ::: "memory")

// ---- flat acq_rel global barrier ----------------------------------------------
__device__ __forceinline__ void gbar2(unsigned* cnt, unsigned* gen, unsigned nb,
                                      unsigned base, unsigned idx) {
    __syncthreads();
    if (threadIdx.x == 0) {
        unsigned old;
        asm volatile("atom.acq_rel.gpu.global.add.u32 %0, [%1], 1;"
                     : "=r"(old) : "l"(cnt) : "memory");
        if (old == nb - 1) {
            asm volatile("st.relaxed.gpu.global.u32 [%0], 0;"
                         :: "l"(cnt) : "memory");
            unsigned d;
            asm volatile("atom.release.gpu.global.add.u32 %0, [%1], 1;"
                         : "=r"(d) : "l"(gen) : "memory");
        } else {
            unsigned g;
            do {
                asm volatile("ld.acquire.gpu.global.u32 %0, [%1];"
                             : "=r"(g) : "l"(gen) : "memory");
            } while ((g - base) < idx);
        }
    }
    __syncthreads();
}

// =================== persistent ODE kernel (fp16 weights, L1-resident) =======
__device__ __forceinline__ float2 rowdot2h(const __half* __restrict__ w0,
                                           const __half* __restrict__ w1,
                                           const float* __restrict__ sv,
                                           int K, int lane) {
    float s0 = 0.f, s1 = 0.f;
#pragma unroll 4
    for (int k = lane * 8; k < K; k += 256) {
        uint4 ua = *(const uint4*)(w0 + k);
        uint4 ub = *(const uint4*)(w1 + k);
        const __half2* ah = (const __half2*)&ua;
        const __half2* bh = (const __half2*)&ub;
        float4 v0 = *(const float4*)(sv + k);
        float4 v1 = *(const float4*)(sv + k + 4);
        float2 a0 = __half22float2(ah[0]), a1 = __half22float2(ah[1]);
        float2 a2 = __half22float2(ah[2]), a3 = __half22float2(ah[3]);
        float2 c0 = __half22float2(bh[0]), c1 = __half22float2(bh[1]);
        float2 c2 = __half22float2(bh[2]), c3 = __half22float2(bh[3]);
        s0 += a0.x * v0.x + a0.y * v0.y + a1.x * v0.z + a1.y * v0.w
            + a2.x * v1.x + a2.y * v1.y + a3.x * v1.z + a3.y * v1.w;
        s1 += c0.x * v0.x + c0.y * v0.y + c1.x * v0.z + c1.y * v0.w
            + c2.x * v1.x + c2.y * v1.y + c3.x * v1.z + c3.y * v1.w;
    }
#pragma unroll
    for (int o = 16; o; o >>= 1) {
        s0 += __shfl_xor_sync(0xffffffffu, s0, o);
        s1 += __shfl_xor_sync(0xffffffffu, s1, o);
    }
    return make_float2(s0, s1);
}

__device__ __forceinline__ float rowdoth(const __half* __restrict__ wr,
                                         const float* __restrict__ sv,
                                         int K, int lane) {
    float s = 0.f;
#pragma unroll 8
    for (int k = lane * 8; k < K; k += 256) {
        uint4 ua = *(const uint4*)(wr + k);
        const __half2* ah = (const __half2*)&ua;
        float4 v0 = *(const float4*)(sv + k);
        float4 v1 = *(const float4*)(sv + k + 4);
        float2 a0 = __half22float2(ah[0]), a1 = __half22float2(ah[1]);
        float2 a2 = __half22float2(ah[2]), a3 = __half22float2(ah[3]);
        s += a0.x * v0.x + a0.y * v0.y + a1.x * v0.z + a1.y * v0.w
           + a2.x * v1.x + a2.y * v1.y + a3.x * v1.z + a3.y * v1.w;
    }
#pragma unroll
    for (int o = 16; o; o >>= 1) s += __shfl_xor_sync(0xffffffffu, s, o);
    return s;
}

__global__ void __launch_bounds__(256, 1) ode_all(
    const float* __restrict__ b1, const float* __restrict__ b2,
    const float* __restrict__ b3) {
    __shared__ __align__(16) float sv[FF];
    __shared__ unsigned sbase;
    int tid = threadIdx.x, lane = tid & 31, warp = tid >> 5;
    int wg = blockIdx.x * 8 + warp;

    if (tid == 0) sbase = *(volatile unsigned*)&g_gen;
    if (blockIdx.x == 0)
        for (int i = tid; i < H; i += 256) __stcg(&g_h[i], 0.f);
    __syncthreads();
    unsigned base = sbase, bi = 0;
    gbar2(&g_cnt, &g_gen, NB, base, ++bi);

    float hreg = 0.f, ks = 0.f;

    for (int iv = 0; iv < NSEG; iv++)
    for (int sb = 0; sb < SUB; sb++)
    for (int m = 0; m < 4; m++) {
        const float* vsrc = (m == 0) ? g_h : g_heff;
        for (int i = tid; i < H; i += 256) sv[i] = __ldcg(vsrc + i);
        __syncthreads();
        {   // stage 1 (2048 rows / 1024 warps; fixed rows -> L1-resident fp16)
            float2 s = rowdot2h(g_O16 + O_W1 + (size_t)wg * H,
                                g_O16 + O_W1 + (size_t)(wg + NWARP) * H,
                                sv, H, lane);
            if (lane == 0) {
                __stcg(&g_t1[wg],         tanhf(s.x + b1[wg]));
                __stcg(&g_t1[wg + NWARP], tanhf(s.y + b1[wg + NWARP]));
            }
        }
        gbar2(&g_cnt, &g_gen, NB, base, ++bi);

        for (int i = tid; i < FF; i += 256) sv[i] = __ldcg(&g_t1[i]);
        __syncthreads();
        {   // stage 2
            float2 s = rowdot2h(g_O16 + O_W2 + (size_t)wg * FF,
                                g_O16 + O_W2 + (size_t)(wg + NWARP) * FF,
                                sv, FF, lane);
            if (lane == 0) {
                __stcg(&g_t2[wg],         tanhf(s.x + b2[wg]));
                __stcg(&g_t2[wg + NWARP], tanhf(s.y + b2[wg + NWARP]));
            }
        }
        gbar2(&g_cnt, &g_gen, NB, base, ++bi);

        for (int i = tid; i < FF; i += 256) sv[i] = __ldcg(&g_t2[i]);
        __syncthreads();
        if (wg < H) {   // stage 3 + RK4 combine
            float s = rowdoth(g_O16 + O_W3 + (size_t)wg * FF, sv, FF, lane);
            if (lane == 0) {
                float kv = s + b3[wg];
                if (m == 0)      { ks = kv;          __stcg(&g_heff[wg], hreg + 0.5f * DT * kv); }
                else if (m == 1) { ks += 2.f * kv;   __stcg(&g_heff[wg], hreg + 0.5f * DT * kv); }
                else if (m == 2) { ks += 2.f * kv;   __stcg(&g_heff[wg], hreg + DT * kv); }
                else {
                    hreg += (DT / 6.f) * (ks + kv);
                    __stcg(&g_h[wg], hreg);
                    if (sb == SUB - 1) g_traj[iv][wg] = hreg;
                }
            }
        }
        gbar2(&g_cnt, &g_gen, NB, base, ++bi);
    }
}

// ---------------- fp16 conversions -------------------------------------------
__global__ void ocvt(const float* __restrict__ w1, const float* __restrict__ w2,
                     const float* __restrict__ w3) {
    size_t i = (size_t)blockIdx.x * 256 + threadIdx.x;   // 8M elems
    float a;
    if (i < O_W2)       a = w1[i];
    else if (i < O_W3)  a = w2[i - O_W2];
    else                a = w3[i - O_W3];
    g_O16[i] = __float2half_rn(a);
}

__global__ void wcvt4(const float* __restrict__ w0, const float* __restrict__ w1,
                      const float* __restrict__ w2, const float* __restrict__ w3) {
    int m = blockIdx.y;
    const float* src = (m == 0) ? w0 : (m == 1) ? w1 : (m == 2) ? w2 : w3;
    size_t i = (size_t)blockIdx.x * 256 + threadIdx.x;
    g_W16[(size_t)m * G3 * H + i] = __float2half_rn(src[i]);
}

__global__ void xcvt(const float* __restrict__ x) {
    size_t i = (size_t)blockIdx.x * 256 + threadIdx.x;
    int m = (int)(i >> 10), k = (int)(i & (H - 1));
    int t = m >> 6, b = m & 63;
    g_X16[i] = __float2half_rn(x[((size_t)b * T + t) * H + k]);
}

__global__ void init_states() {      // <<<RP, H>>>
    int r = blockIdx.x, j = threadIdx.x;
    float v = (r < R) ? g_traj[r & 7][j] : 0.f;
    __half hv16 = __float2half_rn(v);
    size_t o = (size_t)r * H + j;
    g_h1[0][o] = v;  g_h1[1][o] = v;
    g_h2[0][o] = v;  g_h2[1][o] = v;
#pragma unroll
    for (int s = 0; s < 4; s++) g_A16[(size_t)s * RP * H + o] = hv16;
}

// ================== HMMA fp16 core, BK=64 ====================================
__device__ __forceinline__ void mma_core(
    uint32_t sbase, int tid, int lane, int wm, int wn,
    const __half* A, const __half* W,
    int r0, int n0, int kbase, int nst, float acc[4][4][4]) {

    uint32_t aoff = (uint32_t)(wm + (lane & 15)) * RS + ((lane >> 4) << 4);
    uint32_t woff = (uint32_t)(wn + ((lane >> 4) << 3) + (lane & 7)) * RS
                  + (((lane >> 3) & 1) << 4);

    {
        uint32_t sb2 = sbase;
#pragma unroll
        for (int j = 0; j < 4; j++) {
            int u = tid + j * 256;
            int row = u >> 3, kc = (u & 7) << 3;
            uint32_t doff = (uint32_t)row * RS + ((uint32_t)kc << 1);
            cp16cg(sb2 + doff,      A + (size_t)(r0 + row) * H + kbase + kc);
            cp16ca(sb2 + TB + doff, W + (size_t)(n0 + row) * H + kbase + kc);
        }
        CPCOMMIT();
    }

    for (int st = 0; st < nst; st++) {
        if (st + 1 < nst) {
            int kg = kbase + (st + 1) * BK;
            uint32_t sb2 = sbase + ((st + 1) & 1) * SETB;
#pragma unroll
            for (int j = 0; j < 4; j++) {
                int u = tid + j * 256;
                int row = u >> 3, kc = (u & 7) << 3;
                uint32_t doff = (uint32_t)row * RS + ((uint32_t)kc << 1);
                cp16cg(sb2 + doff,      A + (size_t)(r0 + row) * H + kg + kc);
                cp16ca(sb2 + TB + doff, W + (size_t)(n0 + row) * H + kg + kc);
            }
            CPCOMMIT();
            CPWAIT1();
        } else {
            CPWAIT0();
        }
        __syncthreads();

        uint32_t bs = sbase + (st & 1) * SETB;
        uint32_t uA = bs, uW = bs + TB;
#pragma unroll
        for (int kh = 0; kh < 4; kh++) {
            unsigned af[4][4], wf[2][4];
            uint32_t ko = (uint32_t)kh << 5;
#pragma unroll
            for (int mt = 0; mt < 4; mt++)
                ldsm4(af[mt], uA + aoff + mt * 16 * RS + ko);
#pragma unroll
            for (int p = 0; p < 2; p++)
                ldsm4(wf[p], uW + woff + p * 16 * RS + ko);
#pragma unroll
            for (int mt = 0; mt < 4; mt++)
#pragma unroll
                for (int nt = 0; nt < 4; nt++)
                    mma16816(acc[mt][nt], af[mt], &wf[nt >> 1][(nt & 1) * 2]);
        }
        __syncthreads();
    }
}

__device__ __forceinline__ void mma_epi(float* P, int r0, int n0, int kz,
                                        int wm, int wn, int lane,
                                        float acc[4][4][4]) {
    size_t pb = (size_t)kz * ((size_t)RP * G3);
#pragma unroll
    for (int mt = 0; mt < 4; mt++) {
        int row = r0 + wm + mt * 16 + (lane >> 2);
#pragma unroll
        for (int nt = 0; nt < 4; nt++) {
            int col = n0 + wn + nt * 8 + (lane & 3) * 2;
            float2 v0 = {acc[mt][nt][0], acc[mt][nt][1]};
            float2 v1 = {acc[mt][nt][2], acc[mt][nt][3]};
            *(float2*)&P[pb + (size_t)row * G3 + col] = v0;
            *(float2*)&P[pb + (size_t)(row + 8) * G3 + col] = v1;
        }
    }
}

// ================== gi0 GEMM ==================================================
__global__ void __launch_bounds__(256, 2) gi0_mma(const float* __restrict__ bi0) {
    extern __shared__ __align__(16) char dynsm[];
    uint32_t sbase = smem_u32(dynsm);
    int tid = threadIdx.x, wid = tid >> 5, lane = tid & 31;
    const __half* W = g_W16 + 3ull * G3 * H;

    int r0 = blockIdx.x * BM, n0 = blockIdx.y * BN;
    int wm = (wid >> 2) * 64, wn = (wid & 3) * 32;

    float acc[4][4][4] = {};
    mma_core(sbase, tid, lane, wm, wn, g_X16, W, r0, n0, 0, H / BK, acc);

#pragma unroll
    for (int mt = 0; mt < 4; mt++) {
        int row = r0 + wm + mt * 16 + (lane >> 2);
#pragma unroll
        for (int nt = 0; nt < 4; nt++) {
            int col = n0 + wn + nt * 8 + (lane & 3) * 2;
            float b0 = bi0[col], b1 = bi0[col + 1];
            float2 v0 = {acc[mt][nt][0] + b0, acc[mt][nt][1] + b1};
            float2 v1 = {acc[mt][nt][2] + b0, acc[mt][nt][3] + b1};
            *(float2*)&g_gi0[(size_t)row * G3 + col] = v0;
            *(float2*)&g_gi0[(size_t)(row + 8) * G3 + col] = v1;
        }
    }
}

// ---------------- finalizer device functions ----------------------------------
__device__ __forceinline__ void st_hv(int slot, size_t o, const float* hv,
                                      float* hbuf) {
    *(float4*)&hbuf[o] = make_float4(hv[0], hv[1], hv[2], hv[3]);
    __half h16[4];
#pragma unroll
    for (int v = 0; v < 4; v++) h16[v] = __float2half_rn(hv[v]);
    *(uint2*)&g_A16[(size_t)slot * RP * H + o] = *(const uint2*)h16;
}

__device__ __forceinline__ void l0fin_dev(int blk, int tid,
                                          const float* __restrict__ bh0,
                                          int step, int src) {
    int e = (blk * 256 + tid) << 2;
    int r = e >> 10, j = e & 1023;
    size_t base = (size_t)r * G3 + j;
    float acc[3][4] = {};
#pragma unroll
    for (int ks = 0; ks < KS; ks++) {
        const float* p = g_P0 + (size_t)ks * ((size_t)RP * G3) + base;
#pragma unroll
        for (int g = 0; g < 3; g++) {
            float4 v = __ldcg((const float4*)(p + (size_t)g * H));
            acc[g][0] += v.x; acc[g][1] += v.y; acc[g][2] += v.z; acc[g][3] += v.w;
        }
    }
    const float* gi = g_gi0 + ((size_t)((r >> 3) * SEQ + step)) * G3 + j;
    float4 gr = *(const float4*)gi;
    float4 gz = *(const float4*)(gi + H);
    float4 gn = *(const float4*)(gi + 2 * H);
    float4 br = *(const float4*)(bh0 + j);
    float4 bz = *(const float4*)(bh0 + H + j);
    float4 bn = *(const float4*)(bh0 + 2 * H + j);
    size_t o = (size_t)r * H + j;
    float4 hp = __ldcg((const float4*)&g_h1[src][o]);
    float grv[4] = {gr.x, gr.y, gr.z, gr.w}, gzv[4] = {gz.x, gz.y, gz.z, gz.w};
    float gnv[4] = {gn.x, gn.y, gn.z, gn.w}, brv[4] = {br.x, br.y, br.z, br.w};
    float bzv[4] = {bz.x, bz.y, bz.z, bz.w}, bnv[4] = {bn.x, bn.y, bn.z, bn.w};
    float hpv[4] = {hp.x, hp.y, hp.z, hp.w}, hv[4];
#pragma unroll
    for (int v = 0; v < 4; v++) {
        float rg = sigf(grv[v] + acc[0][v] + brv[v]);
        float z  = sigf(gzv[v] + acc[1][v] + bzv[v]);
        float n  = tanhf(gnv[v] + rg * (acc[2][v] + bnv[v]));
        hv[v] = (1.f - z) * n + z * hpv[v];
    }
    int dst = src ^ 1;
    st_hv(dst, o, hv, g_h1[dst]);
}

__device__ __forceinline__ void l1fin_dev(int blk, int tid,
                                          const float* __restrict__ bi1,
                                          const float* __restrict__ bh1,
                                          float* __restrict__ out,
                                          int step, int src) {
    int e = (blk * 256 + tid) << 2;
    int r = e >> 10, j = e & 1023;
    size_t base = (size_t)r * G3 + j;
    float ai[3][4] = {}, ah[3][4] = {};
#pragma unroll
    for (int ks = 0; ks < KS; ks++) {
        const float* pi = g_PI + (size_t)ks * ((size_t)RP * G3) + base;
        const float* ph = g_PH + (size_t)ks * ((size_t)RP * G3) + base;
#pragma unroll
        for (int g = 0; g < 3; g++) {
            float4 vi = __ldcg((const float4*)(pi + (size_t)g * H));
            float4 vh = __ldcg((const float4*)(ph + (size_t)g * H));
            ai[g][0] += vi.x; ai[g][1] += vi.y; ai[g][2] += vi.z; ai[g][3] += vi.w;
            ah[g][0] += vh.x; ah[g][1] += vh.y; ah[g][2] += vh.z; ah[g][3] += vh.w;
        }
    }
    float4 bir = *(const float4*)(bi1 + j);
    float4 biz = *(const float4*)(bi1 + H + j);
    float4 bin = *(const float4*)(bi1 + 2 * H + j);
    float4 bhr = *(const float4*)(bh1 + j);
    float4 bhz = *(const float4*)(bh1 + H + j);
    float4 bhn = *(const float4*)(bh1 + 2 * H + j);
    size_t o = (size_t)r * H + j;
    float4 hp = __ldcg((const float4*)&g_h2[src][o]);
    float birv[4] = {bir.x, bir.y, bir.z, bir.w}, bizv[4] = {biz.x, biz.y, biz.z, biz.w};
    float binv[4] = {bin.x, bin.y, bin.z, bin.w}, bhrv[4] = {bhr.x, bhr.y, bhr.z, bhr.w};
    float bhzv[4] = {bhz.x, bhz.y, bhz.z, bhz.w}, bhnv[4] = {bhn.x, bhn.y, bhn.z, bhn.w};
    float hpv[4] = {hp.x, hp.y, hp.z, hp.w}, hv[4];
#pragma unroll
    for (int v = 0; v < 4; v++) {
        float rg = sigf(ai[0][v] + birv[v] + ah[0][v] + bhrv[v]);
        float z  = sigf(ai[1][v] + bizv[v] + ah[1][v] + bhzv[v]);
        float n  = tanhf(ai[2][v] + binv[v] + rg * (ah[2][v] + bhnv[v]));
        hv[v] = (1.f - z) * n + z * hpv[v];
    }
    int dst = src ^ 1;
    st_hv(2 + dst, o, hv, g_h2[dst]);
    *(float4*)&out[((size_t)step * R + r) * H + j] =
        make_float4(hv[0], hv[1], hv[2], hv[3]);
}

// ================== persistent GRU step kernel ================================
__global__ void __launch_bounds__(256, 2) gru_steps(
    const float* __restrict__ bh0, const float* __restrict__ bi1,
    const float* __restrict__ bh1, float* __restrict__ out) {
    extern __shared__ __align__(16) char dynsm[];
    uint32_t sbase = smem_u32(dynsm);
    __shared__ unsigned sgen;
    int tid = threadIdx.x, wid = tid >> 5, lane = tid & 31;
    int cta = blockIdx.x;
    int wm = (wid >> 2) * 64, wn = (wid & 3) * 32;

    if (tid == 0) sgen = *(volatile unsigned*)&g_gen2;
    __syncthreads();
    unsigned base = sgen, bi = 0;

    // ---- prologue: gh0(0) (96 jobs) ----
    if (cta < 96) {
        int x = cta & 1, y = (cta >> 1) % 24, kz = cta / 48;
        float acc[4][4][4] = {};
        mma_core(sbase, tid, lane, wm, wn, g_A16, g_W16,
                 x * BM, y * BN, kz * KC, KC / BK, acc);
        mma_epi(g_P0, x * BM, y * BN, kz, wm, wn, lane, acc);
    }
    gbar2(&g_cnt2, &g_gen2, SNB, base, ++bi);

    for (int u = cta; u < 240; u += SNB) l0fin_dev(u, tid, bh0, 0, 0);
    gbar2(&g_cnt2, &g_gen2, SNB, base, ++bi);

    // ---- 64 steps ----
    for (int s = 0; s < SEQ; s++) {
        int src = s & 1;
        int njobs = (s == SEQ - 1) ? 192 : 288;
        if (cta < njobs) {
            int x = cta & 1, y = (cta >> 1) % 24, z = cta / 48;
            int prob = z >> 1, kz = z & 1;
            int asel = (prob == 1) ? (2 + src) : (src ^ 1);
            int wsel = (prob == 0) ? 1 : (prob == 1) ? 2 : 0;
            float* P = (prob == 0) ? g_PI : (prob == 1) ? g_PH : g_P0;
            const __half* A = g_A16 + (size_t)asel * RP * H;
            const __half* W = g_W16 + (size_t)wsel * G3 * H;
            float acc[4][4][4] = {};
            mma_core(sbase, tid, lane, wm, wn, A, W,
                     x * BM, y * BN, kz * KC, KC / BK, acc);
            mma_epi(P, x * BM, y * BN, kz, wm, wn, lane, acc);
        }
        gbar2(&g_cnt2, &g_gen2, SNB, base, ++bi);

        int fj = (s == SEQ - 1) ? 240 : 480;
        for (int u = cta; u < fj; u += SNB) {
            if (u < 240) l1fin_dev(u, tid, bi1, bh1, out, s, src);
            else         l0fin_dev(u - 240, tid, bh0, s + 1, src ^ 1);
        }
        gbar2(&g_cnt2, &g_gen2, SNB, base, ++bi);
    }
}

// ---------------- launcher --------------------------------------------------
extern "C" void kernel_launch(void* const* d_in, const int* in_sizes, int n_in,
                              void* d_out, int out_size) {
    const float* x   = (const float*)d_in[0];
    const float* w1  = (const float*)d_in[1];
    const float* b1  = (const float*)d_in[2];
    const float* w2  = (const float*)d_in[3];
    const float* b2  = (const float*)d_in[4];
    const float* w3  = (const float*)d_in[5];
    const float* b3  = (const float*)d_in[6];
    const float* wi0 = (const float*)d_in[7];
    const float* wh0 = (const float*)d_in[8];
    const float* bi0 = (const float*)d_in[9];
    const float* bh0 = (const float*)d_in[10];
    const float* wi1 = (const float*)d_in[11];
    const float* wh1 = (const float*)d_in[12];
    const float* bi1 = (const float*)d_in[13];
    const float* bh1 = (const float*)d_in[14];
    float* out = (float*)d_out;

    static int s_init = 0;
    if (!s_init) {
        cudaFuncSetAttribute(gi0_mma,   cudaFuncAttributeMaxDynamicSharedMemorySize, DSM);
        cudaFuncSetAttribute(gru_steps, cudaFuncAttributeMaxDynamicSharedMemorySize, DSM);
        s_init = 1;
    }

    ocvt<<<(8 * 1024 * 1024) / 256, 256>>>(w1, w2, w3);
    wcvt4<<<dim3((G3 * H) / 256, 4), 256>>>(wh0, wi1, wh1, wi0);
    xcvt<<<(MX * H) / 256, 256>>>(x);

    gi0_mma<<<dim3(MX / BM, G3 / BN), 256, DSM>>>(bi0);
    ode_all<<<NB, 256>>>(b1, b2, b3);
    init_states<<<RP, H>>>();

    gru_steps<<<SNB, 256, DSM>>>(bh0, bi1, bh1, out);
}